// round 7
// baseline (speedup 1.0000x reference)
#include <cuda_runtime.h>
#include <cstdint>

#define NB   8
#define CC   256
#define HH   56
#define WWd  56
#define HWP  3136
#define PPAD 3200
#define K7   7
#define CKD  1792

// Scratch
__device__ float g_Xp [NB * CC  * PPAD];   //  26 MB  A1
__device__ float g_T5 [NB * CKD * PPAD];   // 184 MB  B1 (p contiguous)
__device__ float g_T6t[NB * PPAD * CKD];   // 184 MB  B2 transposed (q contiguous)
__device__ float g_T7 [NB * CC  * CKD];    //  15 MB  A2 (q contiguous)

__device__ __forceinline__ uint32_t smem_u32(const void* p) {
    uint32_t a;
    asm("{ .reg .u64 t; cvta.to.shared.u64 t, %1; cvt.u32.u64 %0, t; }" : "=r"(a) : "l"(p));
    return a;
}
__device__ __forceinline__ float rna_tf32(float x) {
    uint32_t r;
    asm("cvt.rna.tf32.f32 %0, %1;" : "=r"(r) : "f"(x));
    return __uint_as_float(r);
}
__device__ __forceinline__ uint32_t lds32(uint32_t a) {
    uint32_t v;
    asm volatile("ld.shared.b32 %0, [%1];" : "=r"(v) : "r"(a));
    return v;
}
#define CP_ASYNC16(dst, src) \
    asm volatile("cp.async.cg.shared.global [%0], [%1], 16;" :: "r"(dst), "l"(src))
#define CP_COMMIT() asm volatile("cp.async.commit_group;")
#define CP_WAIT1()  asm volatile("cp.async.wait_group 1;" ::: "memory")

// ---------------- prep ----------------
__global__ void prep_xp_kernel(const float* __restrict__ x) {
    int idx = blockIdx.x * blockDim.x + threadIdx.x;
    if (idx >= NB * CC * PPAD) return;
    int p  = idx % PPAD;
    int nc = idx / PPAD;
    g_Xp[idx] = (p < HWP) ? rna_tf32(x[nc * HWP + p]) : 0.0f;
}

// Fused: writes T5[n,q,p] (p-contiguous) and T6t[n,p,q] (q-contiguous via smem transpose)
__global__ __launch_bounds__(256) void prep_t56_kernel(const float* __restrict__ x,
                                                       const float* __restrict__ p1w) {
    __shared__ float ts[64][33];
    int p0 = blockIdx.x * 32;
    int q0 = blockIdx.y * 64;
    int n  = blockIdx.z;
    int t  = threadIdx.x;
    int tp = t & 31;
    int tq = t >> 5;

    const float* xn = x + n * CC * HWP;
    int p = p0 + tp;
    bool pv = (p < HWP);
    int h = p / WWd, w = p % WWd;
    int hh = (h + HH - 1) % HH;
    int w2 = (w + 1) % WWd;
    float* t5n = g_T5 + ((long)n * CKD) * PPAD;

#pragma unroll
    for (int qi = 0; qi < 8; qi++) {
        int ql = tq + 8 * qi;
        int q = q0 + ql;
        float v5 = 0.0f, v6 = 0.0f;
        if (pv) {
            int j = q / K7, k = q % K7;
            int jm = (j + CC - 1) % CC;
            float xv  = xn[j * HWP + p];
            float t1  = p1w[j * HWP + p] * xv;
            float t3 = 0.0f;
            int wk = w + k - 3;
            if (wk >= 0 && wk < WWd) {
                int pp = h * WWd + wk;
                t3 = p1w[jm * HWP + pp] * xn[jm * HWP + pp];
            }
            float t4 = 0.0f;
            int wk2 = w2 + k - 3;
            if (wk2 >= 0 && wk2 < WWd) {
                int pp = hh * WWd + wk2;
                t4 = p1w[jm * HWP + pp] * xn[jm * HWP + pp];
            }
            v5 = rna_tf32(t1 - t3);
            v6 = rna_tf32(xv + t4);
        }
        t5n[(long)q * PPAD + p] = v5;
        ts[ql][tp] = v6;
    }
    __syncthreads();

    int ql = t & 63;
    int pl = t >> 6;
    float* dst = g_T6t + ((long)n * PPAD) * CKD;
#pragma unroll
    for (int pi = 0; pi < 8; pi++) {
        int prow = p0 + pl + 4 * pi;
        dst[(long)prow * CKD + q0 + ql] = ts[ql][pl + 4 * pi];
    }
}

// ---------------- TF32 mma.sync GEMM (NT): C = scale * A(MxK) * B(NxK)^T ----------------
// CTA 128 thr, block 128x128xBK32, 4 warps (2m x 2n), warp 64x64 = 4x8 m16n8k8.
// 3 stages x 32KB = 96KB -> 2 CTAs/SM. Smem elem (row,k) at row*128 + ((k*4)^((row&7)<<4)).
__global__ __launch_bounds__(128, 2)
void gemm_mma(const float* __restrict__ A, const float* __restrict__ B, float* __restrict__ C,
              int K, int KT, long sAz, long sBz, long sCz, int ldc, float scale,
              int nvalid, int round_out) {
    extern __shared__ __align__(1024) char smem[];
    const uint32_t STGB = 32768;   // 16KB A + 16KB B per stage
    uint32_t sb = smem_u32(smem);

    int tid = threadIdx.x, lane = tid & 31, wid = tid >> 5;
    int g = lane >> 2, t = lane & 3;
    int mwarp = (wid & 1) * 64, nwarp = (wid >> 1) * 64;

    const float* Ab = A + (long)blockIdx.z * sAz + (long)(blockIdx.x * 128) * K;
    const float* Bb = B + (long)blockIdx.z * sBz + (long)(blockIdx.y * 128) * K;

    // staging: each thread stages one A row and one B row (8 granules each)
    const char* aSrc = (const char*)(Ab + (long)tid * K);
    const char* bSrc = (const char*)(Bb + (long)tid * K);
    uint32_t aDst = sb + tid * 128;
    uint32_t bDst = sb + 16384 + tid * 128;
    uint32_t swz = (tid & 7) * 16;

    float c[4][8][4];
#pragma unroll
    for (int mi = 0; mi < 4; mi++)
#pragma unroll
        for (int ni = 0; ni < 8; ni++)
#pragma unroll
            for (int e = 0; e < 4; e++) c[mi][ni][e] = 0.0f;

    // prologue: stages 0,1
#pragma unroll
    for (int s = 0; s < 2; s++) {
        uint32_t st = s * STGB;
        long go = (long)s * 128;
#pragma unroll
        for (int j = 0; j < 8; j++) {
            uint32_t off = (uint32_t)((j * 16) ^ swz);
            CP_ASYNC16(aDst + st + off, aSrc + go + j * 16);
            CP_ASYNC16(bDst + st + off, bSrc + go + j * 16);
        }
        CP_COMMIT();
    }

    int buf = 0;   // buffer of stage kt (mod 3)
#pragma unroll 1
    for (int kt = 0; kt < KT; kt++) {
        CP_WAIT1();
        __syncthreads();
        // issue stage kt+2 into buffer (buf+2)%3 (its compute finished last iter)
        if (kt + 2 < KT) {
            int b2 = buf + 2; if (b2 >= 3) b2 -= 3;
            uint32_t st = (uint32_t)b2 * STGB;
            long go = (long)(kt + 2) * 128;
#pragma unroll
            for (int j = 0; j < 8; j++) {
                uint32_t off = (uint32_t)((j * 16) ^ swz);
                CP_ASYNC16(aDst + st + off, aSrc + go + j * 16);
                CP_ASYNC16(bDst + st + off, bSrc + go + j * 16);
            }
        }
        CP_COMMIT();

        uint32_t sA = sb + (uint32_t)buf * STGB;
        uint32_t sB = sA + 16384;
#pragma unroll
        for (int kk = 0; kk < 4; kk++) {
            int k0 = kk * 8;
            uint32_t kx1 = (uint32_t)(((k0 + t) * 4) ^ (g << 4));
            uint32_t kx2 = (uint32_t)(((k0 + t + 4) * 4) ^ (g << 4));
            uint32_t a[4][4];
#pragma unroll
            for (int mi = 0; mi < 4; mi++) {
                uint32_t b0 = sA + (uint32_t)((mwarp + mi * 16 + g) * 128);
                uint32_t b1 = b0 + 8 * 128;
                a[mi][0] = lds32(b0 + kx1);
                a[mi][1] = lds32(b1 + kx1);
                a[mi][2] = lds32(b0 + kx2);
                a[mi][3] = lds32(b1 + kx2);
            }
            uint32_t b[8][2];
#pragma unroll
            for (int ni = 0; ni < 8; ni++) {
                uint32_t nb = sB + (uint32_t)((nwarp + ni * 8 + g) * 128);
                b[ni][0] = lds32(nb + kx1);
                b[ni][1] = lds32(nb + kx2);
            }
#pragma unroll
            for (int mi = 0; mi < 4; mi++)
#pragma unroll
                for (int ni = 0; ni < 8; ni++) {
                    asm volatile(
                        "mma.sync.aligned.m16n8k8.row.col.f32.tf32.tf32.f32 "
                        "{%0,%1,%2,%3}, {%4,%5,%6,%7}, {%8,%9}, {%0,%1,%2,%3};"
                        : "+f"(c[mi][ni][0]), "+f"(c[mi][ni][1]),
                          "+f"(c[mi][ni][2]), "+f"(c[mi][ni][3])
                        : "r"(a[mi][0]), "r"(a[mi][1]), "r"(a[mi][2]), "r"(a[mi][3]),
                          "r"(b[ni][0]), "r"(b[ni][1]));
                }
        }
        buf++; if (buf >= 3) buf = 0;
    }

    // epilogue
    float* Cz = C + (long)blockIdx.z * sCz;
    int colbase = blockIdx.y * 128 + nwarp;
#pragma unroll
    for (int mi = 0; mi < 4; mi++) {
        int row0 = blockIdx.x * 128 + mwarp + mi * 16 + g;
        int row1 = row0 + 8;
#pragma unroll
        for (int ni = 0; ni < 8; ni++) {
            int col = colbase + ni * 8 + 2 * t;
            if (col < nvalid) {
                float2 v0, v1;
                v0.x = c[mi][ni][0] * scale; v0.y = c[mi][ni][1] * scale;
                v1.x = c[mi][ni][2] * scale; v1.y = c[mi][ni][3] * scale;
                if (round_out) {
                    v0.x = rna_tf32(v0.x); v0.y = rna_tf32(v0.y);
                    v1.x = rna_tf32(v1.x); v1.y = rna_tf32(v1.y);
                }
                *(float2*)(Cz + (long)row0 * ldc + col) = v0;
                *(float2*)(Cz + (long)row1 * ldc + col) = v1;
            }
        }
    }
}

// ---------------- launch ----------------
extern "C" void kernel_launch(void* const* d_in, const int* in_sizes, int n_in,
                              void* d_out, int out_size) {
    (void)in_sizes; (void)n_in; (void)out_size;
    const float* x   = (const float*)d_in[0];
    const float* p1w = (const float*)d_in[1];
    float* out = (float*)d_out;

    const int SMEM = 3 * 32768;  // 96 KB -> 2 CTAs/SM
    cudaFuncSetAttribute(gemm_mma, cudaFuncAttributeMaxDynamicSharedMemorySize, SMEM);

    {
        int total = NB * CC * PPAD;
        prep_xp_kernel<<<(total + 255) / 256, 256>>>(x);
    }
    prep_t56_kernel<<<dim3(PPAD / 32, CKD / 64, NB), 256>>>(x, p1w);

    float *T7, *Xp, *T5, *T6t;
    cudaGetSymbolAddress((void**)&T7,  g_T7);
    cudaGetSymbolAddress((void**)&Xp,  g_Xp);
    cudaGetSymbolAddress((void**)&T5,  g_T5);
    cudaGetSymbolAddress((void**)&T6t, g_T6t);

    // GEMM1: T7[i,q] = (1/56) * sum_p Xp[i,p]*T5[q,p];  M=256,N=1792,K=3200
    gemm_mma<<<dim3(CC / 128, CKD / 128, NB), 128, SMEM>>>(
        Xp, T5, T7, PPAD, PPAD / 32,
        (long)CC * PPAD, (long)CKD * PPAD, (long)CC * CKD,
        CKD, 1.0f / 56.0f, CKD, 1);

    // GEMM2: out[i,p] = (1/sqrt(1792)) * sum_q T7[i,q]*T6t[p,q];  M=256,N=3200,K=1792
    gemm_mma<<<dim3(CC / 128, PPAD / 128, NB), 128, SMEM>>>(
        T7, T6t, out, CKD, CKD / 32,
        (long)CC * CKD, (long)PPAD * CKD, (long)CC * HWP,
        HWP, 0.0236227795f, HWP, 0);
}